// round 7
// baseline (speedup 1.0000x reference)
#include <cuda_runtime.h>

// ExtractLearnableSlices — persistent single-wave kernel, grid-stride over
// 8192 (batch, head) tiles with depth-1 software pipeline.
//   x: (B=64, C=64, L=16384) f32
//   channel_params/offset_params: (128,) f32
//   out: (B=64, N=128, W=512) f32
//
// Per tile: stage fused channel lerp v[l] = xf[l]+wc*(xc[l]-xf[l]) over a
// 520-float window (double-buffered smem, one bar/iter), prefetch the next
// tile's window right after the bar, epilogue = 4 outputs/thread time lerp.
// pos = t0 + j in f32, floor via positive int cast — identical to R4.

#define B_DIM   64
#define C_DIM   64
#define L_DIM   16384
#define N_HEADS 128
#define WIDTH   512

#define THREADS 128
#define TILES   (B_DIM * N_HEADS)   // 8192
#define GRID    1776                // 12 blocks/SM * 148 SMs -> single wave
#define SMEM_FLOATS 520             // 130 float4 window

__global__ __launch_bounds__(THREADS, 12) void extract_slices_kernel(
    const float* __restrict__ x,
    const float* __restrict__ channel_params,
    const float* __restrict__ offset_params,
    float* __restrict__ out)
{
    __shared__ float vbuf[2][SMEM_FLOATS];

    const int  tid  = threadIdx.x;
    const bool tail = (tid < 2);

    // ---- param + load-issue helper (exact same math as R4) ----
    float4 ra, rc, rat, rct;        // prefetched window regs (single slot)

    auto setup = [&](int t, float& t0, float& wc, int& l0) {
        const int i = t & (N_HEADS - 1);
        const int b = t >> 7;

        const float cp = __ldg(&channel_params[i]);
        const float op = __ldg(&offset_params[i]);

        const float sc      = 1.0f / (1.0f + expf(-cp));
        const float desired = sc * (float)(C_DIM - 1);   // > 0
        const int   fc      = (int)desired;              // floor (positive)
        const int   cc      = min(fc + 1, C_DIM - 1);
        wc = desired - (float)fc;

        const float so  = 1.0f / (1.0f + expf(-op));
        t0 = so * (float)(L_DIM - WIDTH);                // > 0
        const int pf0 = (int)t0;                         // floor (positive)
        l0 = (pf0 - 1) & ~3;                             // float4-aligned

        const float* __restrict__ xb = x + (size_t)b * (size_t)(C_DIM * L_DIM);
        const float4* __restrict__ f4 = (const float4*)(xb + fc * L_DIM + l0);
        const float4* __restrict__ c4 = (const float4*)(xb + cc * L_DIM + l0);

        ra = f4[tid];
        rc = c4[tid];
        if (tail) { rat = f4[THREADS + tid]; rct = c4[THREADS + tid]; }
    };

    int   cur = blockIdx.x;
    float t0_cur, wc_cur; int l0_cur;
    setup(cur, t0_cur, wc_cur, l0_cur);

    int it = 0;
    for (;;) {
        const int slot = it & 1;
        float* __restrict__ vb = vbuf[slot];
        float4* __restrict__ v4 = (float4*)vb;

        // ---- stage current tile from regs (frees the reg slot) ----
        {
            float4 r;
            r.x = ra.x + wc_cur * (rc.x - ra.x);
            r.y = ra.y + wc_cur * (rc.y - ra.y);
            r.z = ra.z + wc_cur * (rc.z - ra.z);
            r.w = ra.w + wc_cur * (rc.w - ra.w);
            v4[tid] = r;
        }
        if (tail) {
            float4 r;
            r.x = rat.x + wc_cur * (rct.x - rat.x);
            r.y = rat.y + wc_cur * (rct.y - rat.y);
            r.z = rat.z + wc_cur * (rct.z - rat.z);
            r.w = rat.w + wc_cur * (rct.w - rat.w);
            v4[THREADS + tid] = r;
        }
        __syncthreads();   // one bar/iter; double buffer covers WAR across iters

        // ---- prefetch next tile (params + LDGs) under current epilogue ----
        const int nxt = cur + GRID;
        float t0_n = 0.0f, wc_n = 0.0f; int l0_n = 0;
        const bool have_next = (nxt < TILES);
        if (have_next) setup(nxt, t0_n, wc_n, l0_n);

        // ---- epilogue: 4 outputs/thread, coalesced STG, conflict-free LDS ----
        float* __restrict__ orow = out + (size_t)cur * WIDTH + tid;
        const float t0 = t0_cur;
        const int   l0 = l0_cur;

        #pragma unroll
        for (int k = 0; k < 4; ++k) {
            const float pos = t0 + (float)(tid + k * THREADS);  // exact ref f32 math
            const int   pf  = (int)pos;                         // floor (positive)
            const float wt  = pos - (float)pf;
            const int   idx = pf - l0;                          // in [0, 517]
            const float v0  = vb[idx];
            const float v1  = vb[idx + 1];
            orow[k * THREADS] = v0 + wt * (v1 - v0);
        }

        if (!have_next) break;
        cur = nxt; t0_cur = t0_n; wc_cur = wc_n; l0_cur = l0_n; ++it;
    }
}

extern "C" void kernel_launch(void* const* d_in, const int* in_sizes, int n_in,
                              void* d_out, int out_size)
{
    const float* x  = (const float*)d_in[0];
    const float* ch = (const float*)d_in[1];
    const float* of = (const float*)d_in[2];
    float* out = (float*)d_out;

    extract_slices_kernel<<<GRID, THREADS>>>(x, ch, of, out);
}

// round 8
// speedup vs baseline: 1.2113x; 1.2113x over previous
#include <cuda_runtime.h>

// ExtractLearnableSlices — one head x 4 batches per block.
//   x: (B=64, C=64, L=16384) f32
//   channel_params/offset_params: (128,) f32
//   out: (B=64, N=128, W=512) f32
//
// Head params (t0, wc, fc, cc) are batch-invariant: computed once per block
// (2048 outputs). Four batch windows of the fused channel lerp
// v[l] = xf[l] + wc*(xc[l]-xf[l]) are staged into smem (8 independent
// LDG.128/thread), then the epilogue computes pos/floor/wt/idx once per j and
// reuses it across all 4 batches. pos = t0 + j in f32, floor via positive
// int cast — bit-identical to R4's passing math.

#define B_DIM   64
#define C_DIM   64
#define L_DIM   16384
#define N_HEADS 128
#define WIDTH   512

#define THREADS 128
#define NB      4                   // batches per block
#define SMEM_FLOATS 520             // 130 float4 per window

__global__ __launch_bounds__(THREADS) void extract_slices_kernel(
    const float* __restrict__ x,
    const float* __restrict__ channel_params,
    const float* __restrict__ offset_params,
    float* __restrict__ out)
{
    __shared__ float v[NB][SMEM_FLOATS];

    const int tid = threadIdx.x;        // 0..127
    const int i   = blockIdx.x;         // head 0..127
    const int b0  = blockIdx.y * NB;    // first batch

    // ---- per-head params: once per 2048 outputs (exact same math as R4) ----
    const float cp = __ldg(&channel_params[i]);
    const float op = __ldg(&offset_params[i]);

    const float sc      = 1.0f / (1.0f + expf(-cp));
    const float desired = sc * (float)(C_DIM - 1);   // > 0
    const int   fc      = (int)desired;              // floor (positive)
    const int   cc      = min(fc + 1, C_DIM - 1);
    const float wc      = desired - (float)fc;

    const float so  = 1.0f / (1.0f + expf(-op));
    const float t0  = so * (float)(L_DIM - WIDTH);   // > 0
    const int   pf0 = (int)t0;                       // floor (positive)
    const int   l0  = (pf0 - 1) & ~3;                // float4-aligned, slack below

    const int xfo = fc * L_DIM + l0;                 // batch-invariant offsets
    const int xco = cc * L_DIM + l0;

    const bool tail = (tid < 2);

    // ---- stage 4 batch windows; loads grouped for MLP ----
    float4 a[NB], c[NB], at[NB], ct[NB];
    #pragma unroll
    for (int bb = 0; bb < NB; ++bb) {
        const size_t base = (size_t)(b0 + bb) * (size_t)(C_DIM * L_DIM);
        const float4* __restrict__ f4 = (const float4*)(x + base + xfo);
        const float4* __restrict__ c4 = (const float4*)(x + base + xco);
        a[bb] = f4[tid];
        c[bb] = c4[tid];
        if (tail) { at[bb] = f4[THREADS + tid]; ct[bb] = c4[THREADS + tid]; }
    }

    #pragma unroll
    for (int bb = 0; bb < NB; ++bb) {
        float4* __restrict__ v4 = (float4*)v[bb];
        float4 r;
        r.x = a[bb].x + wc * (c[bb].x - a[bb].x);
        r.y = a[bb].y + wc * (c[bb].y - a[bb].y);
        r.z = a[bb].z + wc * (c[bb].z - a[bb].z);
        r.w = a[bb].w + wc * (c[bb].w - a[bb].w);
        v4[tid] = r;
        if (tail) {
            float4 rt;
            rt.x = at[bb].x + wc * (ct[bb].x - at[bb].x);
            rt.y = at[bb].y + wc * (ct[bb].y - at[bb].y);
            rt.z = at[bb].z + wc * (ct[bb].z - at[bb].z);
            rt.w = at[bb].w + wc * (ct[bb].w - at[bb].w);
            v4[THREADS + tid] = rt;
        }
    }
    __syncthreads();

    // ---- epilogue: idx/wt once per j, reused across 4 batches ----
    // out[b][i][j]; j = tid + k*128 (coalesced STG, conflict-free LDS)
    const size_t orow_stride = (size_t)N_HEADS * WIDTH;   // per-batch stride
    float* __restrict__ obase =
        out + ((size_t)b0 * N_HEADS + i) * WIDTH + tid;

    #pragma unroll
    for (int k = 0; k < 4; ++k) {
        const float pos = t0 + (float)(tid + k * THREADS);  // exact ref f32 math
        const int   pf  = (int)pos;                         // floor (positive)
        const float wt  = pos - (float)pf;
        const int   idx = pf - l0;                          // in [0, 517]

        float* __restrict__ o = obase + k * THREADS;
        #pragma unroll
        for (int bb = 0; bb < NB; ++bb) {
            const float v0 = v[bb][idx];
            const float v1 = v[bb][idx + 1];
            o[bb * orow_stride] = v0 + wt * (v1 - v0);
        }
    }
}

extern "C" void kernel_launch(void* const* d_in, const int* in_sizes, int n_in,
                              void* d_out, int out_size)
{
    const float* x  = (const float*)d_in[0];
    const float* ch = (const float*)d_in[1];
    const float* of = (const float*)d_in[2];
    float* out = (float*)d_out;

    dim3 grid(N_HEADS, B_DIM / NB);
    extract_slices_kernel<<<grid, THREADS>>>(x, ch, of, out);
}